// round 1
// baseline (speedup 1.0000x reference)
#include <cuda_runtime.h>
#include <cuda_bf16.h>

// Problem constants
#define IN_F   4096
#define OUT_F  4096
#define M_TOT  16384            // 8 * 2048
#define GROUPS_PER_ROW (IN_F / 32)   // 128

// Dequantized, transposed weight: Wt[k][n], fp32. 64 MB static device buffer.
__device__ float g_Wt[(size_t)IN_F * OUT_F];

// ---------------------------------------------------------------------------
// Kernel 1: 3-bit block dequant -> g_Wt[k][n] (transposed so GEMM B-loads are
// coalesced). Each thread handles one group of 32 weights. Threads in a block
// share the same k-range and have consecutive n -> stores are fully coalesced.
// ---------------------------------------------------------------------------
__global__ void dequant3_kernel(const int* __restrict__ q3,
                                const float* __restrict__ norm) {
    int o    = blockIdx.x * blockDim.x + threadIdx.x;   // output feature n
    int iblk = blockIdx.y;                              // which 32-group along K
    if (o >= OUT_F) return;

    int g = o * GROUPS_PER_ROW + iblk;                  // group index
    const int* b = q3 + (size_t)g * 12;                 // 12 "bytes" as int32
    float nm = norm[g];
    float s  = 2.0f * nm / 7.0f;                        // w = v*s - nm
    int kbase = iblk * 32;

    #pragma unroll
    for (int t = 0; t < 4; t++) {
        int b0 = b[3 * t + 0];
        int b1 = b[3 * t + 1];
        int b2 = b[3 * t + 2];
        int v0 =  b0        & 7;
        int v1 = (b0 >> 3)  & 7;
        int v2 = ((b0 >> 6) & 3) | ((b1 & 1) << 2);
        int v3 = (b1 >> 1)  & 7;
        int v4 = (b1 >> 4)  & 7;
        int v5 = ((b1 >> 7) & 1) | ((b2 & 3) << 1);
        int v6 = (b2 >> 2)  & 7;
        int v7 = (b2 >> 5)  & 7;

        int k = kbase + t * 8;
        g_Wt[(size_t)(k + 0) * OUT_F + o] = (float)v0 * s - nm;
        g_Wt[(size_t)(k + 1) * OUT_F + o] = (float)v1 * s - nm;
        g_Wt[(size_t)(k + 2) * OUT_F + o] = (float)v2 * s - nm;
        g_Wt[(size_t)(k + 3) * OUT_F + o] = (float)v3 * s - nm;
        g_Wt[(size_t)(k + 4) * OUT_F + o] = (float)v4 * s - nm;
        g_Wt[(size_t)(k + 5) * OUT_F + o] = (float)v5 * s - nm;
        g_Wt[(size_t)(k + 6) * OUT_F + o] = (float)v6 * s - nm;
        g_Wt[(size_t)(k + 7) * OUT_F + o] = (float)v7 * s - nm;
    }
}

// ---------------------------------------------------------------------------
// Kernel 2: fp32 SMEM-tiled GEMM  out[m][n] = sum_k X[m][k] * Wt[k][n] + bias[n]
// BM=BN=128, BK=16, 256 threads, 8x8 per-thread microtile.
// ---------------------------------------------------------------------------
#define BM 128
#define BN 128
#define BK 16
#define TM 8
#define TN 8

__global__ __launch_bounds__(256, 2)
void sgemm_bias_kernel(const float* __restrict__ X,
                       const float* __restrict__ bias,
                       float* __restrict__ out) {
    __shared__ float As[BK][BM];       // A stored k-major for stride-1 m reads
    __shared__ float Bs[BK][BN];

    int tid = threadIdx.x;
    int bn  = blockIdx.x * BN;
    int bm  = blockIdx.y * BM;

    int tx = tid & 15;                  // 0..15  -> n microtile
    int ty = tid >> 4;                  // 0..15  -> m microtile

    float acc[TM][TN];
    #pragma unroll
    for (int i = 0; i < TM; i++)
        #pragma unroll
        for (int j = 0; j < TN; j++)
            acc[i][j] = 0.0f;

    // A-tile load mapping: 128 rows x 16 cols = 2048 floats / 256 thr = 2 float4
    int a_row = tid >> 2;               // 0..63 (two halves of 64)
    int a_col = (tid & 3) * 4;          // 0,4,8,12
    // B-tile load mapping: 16 rows x 128 cols / 256 thr = 2 float4
    int b_row = tid >> 5;               // 0..7 (two halves of 8)
    int b_col = (tid & 31) * 4;         // 0..124

    const float* Xp = X + (size_t)bm * IN_F;

    for (int k0 = 0; k0 < IN_F; k0 += BK) {
        // Load A tile (transpose into As[k][m])
        #pragma unroll
        for (int h = 0; h < 2; h++) {
            int m = a_row + h * 64;
            float4 va = *(const float4*)(Xp + (size_t)m * IN_F + k0 + a_col);
            As[a_col + 0][m] = va.x;
            As[a_col + 1][m] = va.y;
            As[a_col + 2][m] = va.z;
            As[a_col + 3][m] = va.w;
        }
        // Load B tile (already k-major in g_Wt)
        #pragma unroll
        for (int h = 0; h < 2; h++) {
            int kr = b_row + h * 8;
            float4 vb = *(const float4*)(&g_Wt[(size_t)(k0 + kr) * OUT_F + bn + b_col]);
            *(float4*)(&Bs[kr][b_col]) = vb;
        }
        __syncthreads();

        #pragma unroll
        for (int k = 0; k < BK; k++) {
            float a[TM], b[TN];
            #pragma unroll
            for (int i = 0; i < TM; i++) a[i] = As[k][ty * TM + i];
            #pragma unroll
            for (int j = 0; j < TN; j++) b[j] = Bs[k][tx * TN + j];
            #pragma unroll
            for (int i = 0; i < TM; i++)
                #pragma unroll
                for (int j = 0; j < TN; j++)
                    acc[i][j] = fmaf(a[i], b[j], acc[i][j]);
        }
        __syncthreads();
    }

    // Epilogue: add bias, store
    #pragma unroll
    for (int i = 0; i < TM; i++) {
        int m = bm + ty * TM + i;
        #pragma unroll
        for (int j = 0; j < TN; j += 4) {
            int n = bn + tx * TN + j;
            float4 r;
            r.x = acc[i][j + 0] + bias[n + 0];
            r.y = acc[i][j + 1] + bias[n + 1];
            r.z = acc[i][j + 2] + bias[n + 2];
            r.w = acc[i][j + 3] + bias[n + 3];
            *(float4*)(&out[(size_t)m * OUT_F + n]) = r;
        }
    }
}

// ---------------------------------------------------------------------------
// Launch
// ---------------------------------------------------------------------------
extern "C" void kernel_launch(void* const* d_in, const int* in_sizes, int n_in,
                              void* d_out, int out_size) {
    const float* x    = (const float*)d_in[0];   // [8, 2048, 4096] f32
    const int*   q3   = (const int*)d_in[1];     // [524288, 12] int32 (byte values)
    const float* norm = (const float*)d_in[2];   // [524288, 1] f32
    const float* bias = (const float*)d_in[3];   // [4096] f32
    float* out = (float*)d_out;                  // [8, 2048, 4096] f32

    (void)in_sizes; (void)n_in; (void)out_size;

    // 1) dequantize weights into g_Wt[k][n]
    dim3 dq_grid(OUT_F / 256, GROUPS_PER_ROW);
    dequant3_kernel<<<dq_grid, 256>>>(q3, norm);

    // 2) GEMM + bias
    dim3 gm_grid(OUT_F / BN, M_TOT / BM);        // (32, 128)
    sgemm_bias_kernel<<<gm_grid, 256>>>(x, bias, out);
}

// round 6
// speedup vs baseline: 7.1391x; 7.1391x over previous
#include <cuda_runtime.h>
#include <cuda_fp16.h>
#include <cstdint>
#include <cstddef>

// ---------------------------------------------------------------------------
// Problem constants
// ---------------------------------------------------------------------------
#define IN_F   4096
#define OUT_F  4096
#define M_TOT  16384            // 8 * 2048

// GEMM tiling
#define BM 128
#define BN 128
#define BK 64
#define KITERS (IN_F / BK)      // 64
#define STAGES 4
#define THREADS 256
#define A_ST (BM * BK * 2)      // 16384 bytes
#define B_ST (BN * BK * 2)      // 16384 bytes
#define STAGE_BYTES (A_ST + B_ST)
#define SMEM_TOTAL (STAGES * STAGE_BYTES)   // 131072

// fp16 staging buffers (static device globals: no allocation)
__device__ __half g_Xh[(size_t)M_TOT * IN_F];    // [m][k] k-contiguous
__device__ __half g_Wh[(size_t)OUT_F * IN_F];    // [o][k] k-contiguous

// ---------------------------------------------------------------------------
// helpers
// ---------------------------------------------------------------------------
__device__ __forceinline__ uint32_t smem_u32(const void* p) {
    uint32_t a;
    asm("{ .reg .u64 t; cvta.to.shared.u64 t, %1; cvt.u32.u64 %0, t; }"
        : "=r"(a) : "l"(p));
    return a;
}
// XOR swizzle for 128B rows: chunk(16B) index bits[6:4] ^= row bits[9:7]
__device__ __forceinline__ uint32_t swz(uint32_t byte_off) {
    return byte_off ^ ((byte_off >> 3) & 0x70);
}
__device__ __forceinline__ void cp_async16(uint32_t saddr, const void* gptr) {
    asm volatile("cp.async.cg.shared.global [%0], [%1], 16;"
                 :: "r"(saddr), "l"(gptr));
}
__device__ __forceinline__ void cp_commit() {
    asm volatile("cp.async.commit_group;");
}
template <int N>
__device__ __forceinline__ void cp_wait() {
    asm volatile("cp.async.wait_group %0;" :: "n"(N));
}
__device__ __forceinline__ void ldmatrix_x4(uint32_t& r0, uint32_t& r1,
                                            uint32_t& r2, uint32_t& r3,
                                            uint32_t addr) {
    asm volatile("ldmatrix.sync.aligned.m8n8.x4.shared.b16 {%0,%1,%2,%3}, [%4];"
                 : "=r"(r0), "=r"(r1), "=r"(r2), "=r"(r3) : "r"(addr));
}
__device__ __forceinline__ void mma16816(float& c0, float& c1, float& c2, float& c3,
                                         uint32_t a0, uint32_t a1, uint32_t a2, uint32_t a3,
                                         uint32_t b0, uint32_t b1) {
    asm volatile(
        "mma.sync.aligned.m16n8k16.row.col.f32.f16.f16.f32 "
        "{%0,%1,%2,%3}, {%4,%5,%6,%7}, {%8,%9}, {%0,%1,%2,%3};"
        : "+f"(c0), "+f"(c1), "+f"(c2), "+f"(c3)
        : "r"(a0), "r"(a1), "r"(a2), "r"(a3), "r"(b0), "r"(b1));
}

// ---------------------------------------------------------------------------
// Prekernel 1: x (fp32) -> g_Xh (fp16)
// ---------------------------------------------------------------------------
__global__ void convert_x_kernel(const float4* __restrict__ x4) {
    size_t i = (size_t)blockIdx.x * blockDim.x + threadIdx.x;
    float4 v = x4[i];
    __half2 h0 = __floats2half2_rn(v.x, v.y);
    __half2 h1 = __floats2half2_rn(v.z, v.w);
    __half2* dst = reinterpret_cast<__half2*>(g_Xh) + 2 * i;
    dst[0] = h0;
    dst[1] = h1;
}

// ---------------------------------------------------------------------------
// Prekernel 2: 3-bit dequant -> g_Wh fp16 [o][k]  (w = n*(2v-7)/7)
// ---------------------------------------------------------------------------
__global__ void dequant3_f16_kernel(const int* __restrict__ q3,
                                    const float* __restrict__ norm) {
    int g = blockIdx.x * blockDim.x + threadIdx.x;   // 524288 groups
    const uint4* q = reinterpret_cast<const uint4*>(q3 + (size_t)g * 12);
    uint4 qa = q[0], qb = q[1], qc = q[2];
    int by[12] = {(int)qa.x, (int)qa.y, (int)qa.z, (int)qa.w,
                  (int)qb.x, (int)qb.y, (int)qb.z, (int)qb.w,
                  (int)qc.x, (int)qc.y, (int)qc.z, (int)qc.w};
    float nm = norm[g];
    float s  = nm * (1.0f / 7.0f);

    __half hv[32];
    #pragma unroll
    for (int t = 0; t < 4; t++) {
        int b0 = by[3 * t + 0], b1 = by[3 * t + 1], b2 = by[3 * t + 2];
        int v[8];
        v[0] =  b0        & 7;
        v[1] = (b0 >> 3)  & 7;
        v[2] = ((b0 >> 6) & 3) | ((b1 & 1) << 2);
        v[3] = (b1 >> 1)  & 7;
        v[4] = (b1 >> 4)  & 7;
        v[5] = ((b1 >> 7) & 1) | ((b2 & 3) << 1);
        v[6] = (b2 >> 2)  & 7;
        v[7] = (b2 >> 5)  & 7;
        #pragma unroll
        for (int j = 0; j < 8; j++)
            hv[t * 8 + j] = __float2half_rn((float)(2 * v[j] - 7) * s);
    }
    uint4* dst = reinterpret_cast<uint4*>(g_Wh + (size_t)g * 32);
    const uint4* src = reinterpret_cast<const uint4*>(hv);
    dst[0] = src[0]; dst[1] = src[1]; dst[2] = src[2]; dst[3] = src[3];
}

// ---------------------------------------------------------------------------
// GEMM: out[m][n] = sum_k Xh[m][k]*Wh[n][k] + bias[n]
// mma.sync m16n8k16 + cp.async 4-stage pipeline.
// 8 warps: wm = wid%4 (32 rows each), wn = wid/4 (64 cols each).
// ---------------------------------------------------------------------------
__global__ __launch_bounds__(THREADS, 1)
void gemm_hmma_kernel(const float* __restrict__ bias,
                      float* __restrict__ out) {
    extern __shared__ char smem[];
    uint32_t sb = smem_u32(smem);

    int tid  = threadIdx.x;
    int wid  = tid >> 5;
    int lane = tid & 31;
    int wm = wid & 3;          // 0..3
    int wn = wid >> 2;         // 0..1

    int bm = blockIdx.y * BM;
    int bn = blockIdx.x * BN;

    const __half* gA = g_Xh + (size_t)bm * IN_F;
    const __half* gB = g_Wh + (size_t)bn * IN_F;

    // per-thread cp.async mapping: 4 chunks of 16B for A, 4 for B, per stage
    int cid_row = 0, cid_c = 0; (void)cid_row; (void)cid_c;

    auto load_stage = [&](int s, int it) {
        uint32_t sA = sb + s * STAGE_BYTES;
        uint32_t sB = sA + A_ST;
        int k0 = it * BK;
        #pragma unroll
        for (int i = 0; i < 4; i++) {
            int id  = tid + i * THREADS;      // 0..1023
            int row = id >> 3;                // 0..127
            int c   = id & 7;                 // 16B chunk in 128B row
            cp_async16(sA + swz(row * 128 + c * 16),
                       gA + (size_t)row * IN_F + k0 + c * 8);
        }
        #pragma unroll
        for (int i = 0; i < 4; i++) {
            int id  = tid + i * THREADS;
            int row = id >> 3;
            int c   = id & 7;
            cp_async16(sB + swz(row * 128 + c * 16),
                       gB + (size_t)row * IN_F + k0 + c * 8);
        }
        cp_commit();
    };

    float acc[2][8][4];
    #pragma unroll
    for (int mt = 0; mt < 2; mt++)
        #pragma unroll
        for (int nt = 0; nt < 8; nt++)
            #pragma unroll
            for (int r = 0; r < 4; r++)
                acc[mt][nt][r] = 0.0f;

    // prologue: fill STAGES-1 stages
    #pragma unroll
    for (int s = 0; s < STAGES - 1; s++) load_stage(s, s);

    // ldmatrix lane addressing (constant per thread)
    // A: matrices {m0-7,k0-7},{m8-15,k0-7},{m0-7,k8-15},{m8-15,k8-15}
    int a_m = (lane & 7) + ((lane >> 3) & 1) * 8;   // row within m16 tile
    int a_kb = (lane >> 4) * 16;                    // byte offset within k16 (2 halves*8)
    // B: matrices {n0-7,k0-7},{n0-7,k8-15},{n8-15,k0-7},{n8-15,k8-15}
    int b_n = (lane & 7) + (lane >> 4) * 8;         // row within n16 group
    int b_kb = ((lane >> 3) & 1) * 16;

    for (int it = 0; it < KITERS; ++it) {
        cp_wait<STAGES - 2>();
        __syncthreads();

        int s = it & (STAGES - 1);
        uint32_t sA = sb + s * STAGE_BYTES;
        uint32_t sB = sA + A_ST;

        // issue load for the stage freed at the previous iteration
        if (it + STAGES - 1 < KITERS)
            load_stage((it + STAGES - 1) & (STAGES - 1), it + STAGES - 1);
        else
            cp_commit();   // keep group accounting uniform

        #pragma unroll
        for (int kc = 0; kc < 4; kc++) {         // four k16 chunks in BK=64
            uint32_t a[2][4];
            #pragma unroll
            for (int mt = 0; mt < 2; mt++) {
                int m_row = wm * 32 + mt * 16 + a_m;
                ldmatrix_x4(a[mt][0], a[mt][1], a[mt][2], a[mt][3],
                            sA + swz(m_row * 128 + kc * 32 + a_kb));
            }
            uint32_t b[8][2];
            #pragma unroll
            for (int ng = 0; ng < 4; ng++) {     // each x4 covers two n8 tiles
                uint32_t r0, r1, r2, r3;
                int n_row = wn * 64 + ng * 16 + b_n;
                ldmatrix_x4(r0, r1, r2, r3,
                            sB + swz(n_row * 128 + kc * 32 + b_kb));
                b[ng * 2 + 0][0] = r0; b[ng * 2 + 0][1] = r1;
                b[ng * 2 + 1][0] = r2; b[ng * 2 + 1][1] = r3;
            }
            #pragma unroll
            for (int mt = 0; mt < 2; mt++)
                #pragma unroll
                for (int nt = 0; nt < 8; nt++)
                    mma16816(acc[mt][nt][0], acc[mt][nt][1],
                             acc[mt][nt][2], acc[mt][nt][3],
                             a[mt][0], a[mt][1], a[mt][2], a[mt][3],
                             b[nt][0], b[nt][1]);
        }
        __syncthreads();
    }

    // epilogue: c frag mapping: rows (lane>>2, +8), cols (lane&3)*2, +1
    #pragma unroll
    for (int mt = 0; mt < 2; mt++) {
        int row0 = bm + wm * 32 + mt * 16 + (lane >> 2);
        #pragma unroll
        for (int nt = 0; nt < 8; nt++) {
            int col = bn + wn * 64 + nt * 8 + (lane & 3) * 2;
            float2 bv = *reinterpret_cast<const float2*>(bias + col);
            float2 v0 = {acc[mt][nt][0] + bv.x, acc[mt][nt][1] + bv.y};
            float2 v1 = {acc[mt][nt][2] + bv.x, acc[mt][nt][3] + bv.y};
            *reinterpret_cast<float2*>(out + (size_t)row0 * OUT_F + col) = v0;
            *reinterpret_cast<float2*>(out + (size_t)(row0 + 8) * OUT_F + col) = v1;
        }
    }
}

// ---------------------------------------------------------------------------
// Launch
// ---------------------------------------------------------------------------
extern "C" void kernel_launch(void* const* d_in, const int* in_sizes, int n_in,
                              void* d_out, int out_size) {
    const float* x    = (const float*)d_in[0];   // [8,2048,4096] f32
    const int*   q3   = (const int*)d_in[1];     // [524288,12] int32 bytes
    const float* norm = (const float*)d_in[2];   // [524288,1] f32
    const float* bias = (const float*)d_in[3];   // [4096] f32
    float* out = (float*)d_out;
    (void)in_sizes; (void)n_in; (void)out_size;

    convert_x_kernel<<<(M_TOT * (size_t)IN_F / 4) / 256, 256>>>(
        reinterpret_cast<const float4*>(x));
    dequant3_f16_kernel<<<(OUT_F * IN_F / 32) / 256, 256>>>(q3, norm);

    cudaFuncSetAttribute(gemm_hmma_kernel,
                         cudaFuncAttributeMaxDynamicSharedMemorySize, SMEM_TOTAL);
    dim3 grid(OUT_F / BN, M_TOT / BM);   // (32, 128)
    gemm_hmma_kernel<<<grid, THREADS, SMEM_TOTAL>>>(bias, out);
}

// round 7
// speedup vs baseline: 8.2853x; 1.1606x over previous
#include <cuda_runtime.h>
#include <cuda_fp16.h>
#include <cstdint>
#include <cstddef>

// ---------------------------------------------------------------------------
// Problem constants
// ---------------------------------------------------------------------------
#define IN_F   4096
#define OUT_F  4096
#define M_TOT  16384            // 8 * 2048

// GEMM tiling
#define BM 128
#define BN 256
#define BK 64
#define KITERS (IN_F / BK)      // 64
#define STAGES 4
#define THREADS 256
#define A_ST (BM * BK * 2)      // 16384 bytes
#define B_ST (BN * BK * 2)      // 32768 bytes
#define STAGE_BYTES (A_ST + B_ST)          // 49152
#define SMEM_TOTAL (STAGES * STAGE_BYTES)  // 196608

// fp16 staging buffers (static device globals: no allocation)
__device__ __half g_Xh[(size_t)M_TOT * IN_F];    // [m][k] k-contiguous
__device__ __half g_Wh[(size_t)OUT_F * IN_F];    // [o][k] k-contiguous

// ---------------------------------------------------------------------------
// helpers
// ---------------------------------------------------------------------------
__device__ __forceinline__ uint32_t smem_u32(const void* p) {
    uint32_t a;
    asm("{ .reg .u64 t; cvta.to.shared.u64 t, %1; cvt.u32.u64 %0, t; }"
        : "=r"(a) : "l"(p));
    return a;
}
// XOR swizzle for 128B rows: chunk(16B) index bits[6:4] ^= row bits[9:7]
__device__ __forceinline__ uint32_t swz(uint32_t byte_off) {
    return byte_off ^ ((byte_off >> 3) & 0x70);
}
__device__ __forceinline__ void cp_async16(uint32_t saddr, const void* gptr) {
    asm volatile("cp.async.cg.shared.global [%0], [%1], 16;"
                 :: "r"(saddr), "l"(gptr));
}
__device__ __forceinline__ void cp_commit() {
    asm volatile("cp.async.commit_group;");
}
template <int N>
__device__ __forceinline__ void cp_wait() {
    asm volatile("cp.async.wait_group %0;" :: "n"(N));
}
__device__ __forceinline__ void ldmatrix_x4(uint32_t& r0, uint32_t& r1,
                                            uint32_t& r2, uint32_t& r3,
                                            uint32_t addr) {
    asm volatile("ldmatrix.sync.aligned.m8n8.x4.shared.b16 {%0,%1,%2,%3}, [%4];"
                 : "=r"(r0), "=r"(r1), "=r"(r2), "=r"(r3) : "r"(addr));
}
__device__ __forceinline__ void mma16816(float& c0, float& c1, float& c2, float& c3,
                                         uint32_t a0, uint32_t a1, uint32_t a2, uint32_t a3,
                                         uint32_t b0, uint32_t b1) {
    asm volatile(
        "mma.sync.aligned.m16n8k16.row.col.f32.f16.f16.f32 "
        "{%0,%1,%2,%3}, {%4,%5,%6,%7}, {%8,%9}, {%0,%1,%2,%3};"
        : "+f"(c0), "+f"(c1), "+f"(c2), "+f"(c3)
        : "r"(a0), "r"(a1), "r"(a2), "r"(a3), "r"(b0), "r"(b1));
}

// ---------------------------------------------------------------------------
// Prekernel 1: x (fp32) -> g_Xh (fp16)
// ---------------------------------------------------------------------------
__global__ void convert_x_kernel(const float4* __restrict__ x4) {
    size_t i = (size_t)blockIdx.x * blockDim.x + threadIdx.x;
    float4 v = x4[i];
    __half2 h0 = __floats2half2_rn(v.x, v.y);
    __half2 h1 = __floats2half2_rn(v.z, v.w);
    __half2* dst = reinterpret_cast<__half2*>(g_Xh) + 2 * i;
    dst[0] = h0;
    dst[1] = h1;
}

// ---------------------------------------------------------------------------
// Prekernel 2: 3-bit dequant -> g_Wh fp16 [o][k]  (w = n*(2v-7)/7)
// ---------------------------------------------------------------------------
__global__ void dequant3_f16_kernel(const int* __restrict__ q3,
                                    const float* __restrict__ norm) {
    int g = blockIdx.x * blockDim.x + threadIdx.x;   // 524288 groups
    const uint4* q = reinterpret_cast<const uint4*>(q3 + (size_t)g * 12);
    uint4 qa = q[0], qb = q[1], qc = q[2];
    int by[12] = {(int)qa.x, (int)qa.y, (int)qa.z, (int)qa.w,
                  (int)qb.x, (int)qb.y, (int)qb.z, (int)qb.w,
                  (int)qc.x, (int)qc.y, (int)qc.z, (int)qc.w};
    float nm = norm[g];
    float s  = nm * (1.0f / 7.0f);

    __half hv[32];
    #pragma unroll
    for (int t = 0; t < 4; t++) {
        int b0 = by[3 * t + 0], b1 = by[3 * t + 1], b2 = by[3 * t + 2];
        int v[8];
        v[0] =  b0        & 7;
        v[1] = (b0 >> 3)  & 7;
        v[2] = ((b0 >> 6) & 3) | ((b1 & 1) << 2);
        v[3] = (b1 >> 1)  & 7;
        v[4] = (b1 >> 4)  & 7;
        v[5] = ((b1 >> 7) & 1) | ((b2 & 3) << 1);
        v[6] = (b2 >> 2)  & 7;
        v[7] = (b2 >> 5)  & 7;
        #pragma unroll
        for (int j = 0; j < 8; j++)
            hv[t * 8 + j] = __float2half_rn((float)(2 * v[j] - 7) * s);
    }
    uint4* dst = reinterpret_cast<uint4*>(g_Wh + (size_t)g * 32);
    const uint4* src = reinterpret_cast<const uint4*>(hv);
    dst[0] = src[0]; dst[1] = src[1]; dst[2] = src[2]; dst[3] = src[3];
}

// ---------------------------------------------------------------------------
// GEMM: out[m][n] = sum_k Xh[m][k]*Wh[n][k] + bias[n]
// mma.sync m16n8k16 + cp.async 4-stage pipeline.
// 8 warps, 2x4 layout: wm = wid&1 (64 rows each), wn = wid>>1 (64 cols each).
// Warp tile 64x64: 4 A-ldsm + 4 B-ldsm per k16 chunk for 32 MMAs.
// ---------------------------------------------------------------------------
__global__ __launch_bounds__(THREADS, 1)
void gemm_hmma_kernel(const float* __restrict__ bias,
                      float* __restrict__ out) {
    extern __shared__ char smem[];
    uint32_t sb = smem_u32(smem);

    int tid  = threadIdx.x;
    int wid  = tid >> 5;
    int lane = tid & 31;
    int wm = wid & 1;          // 0..1 -> 64-row slice
    int wn = wid >> 1;         // 0..3 -> 64-col slice

    int bm = blockIdx.y * BM;
    int bn = blockIdx.x * BN;

    const __half* gA = g_Xh + (size_t)bm * IN_F;
    const __half* gB = g_Wh + (size_t)bn * IN_F;

    auto load_stage = [&](int s, int it) {
        uint32_t sA = sb + s * STAGE_BYTES;
        uint32_t sB = sA + A_ST;
        int k0 = it * BK;
        // A: 128 rows x 8 chunks = 1024 -> 4 per thread
        #pragma unroll
        for (int i = 0; i < 4; i++) {
            int id  = tid + i * THREADS;
            int row = id >> 3;
            int c   = id & 7;
            cp_async16(sA + swz(row * 128 + c * 16),
                       gA + (size_t)row * IN_F + k0 + c * 8);
        }
        // B: 256 rows x 8 chunks = 2048 -> 8 per thread
        #pragma unroll
        for (int i = 0; i < 8; i++) {
            int id  = tid + i * THREADS;
            int row = id >> 3;
            int c   = id & 7;
            cp_async16(sB + swz(row * 128 + c * 16),
                       gB + (size_t)row * IN_F + k0 + c * 8);
        }
        cp_commit();
    };

    float acc[4][8][4];
    #pragma unroll
    for (int mt = 0; mt < 4; mt++)
        #pragma unroll
        for (int nt = 0; nt < 8; nt++)
            #pragma unroll
            for (int r = 0; r < 4; r++)
                acc[mt][nt][r] = 0.0f;

    // prologue
    #pragma unroll
    for (int s = 0; s < STAGES - 1; s++) load_stage(s, s);

    // ldmatrix lane addressing
    int a_m  = (lane & 7) + ((lane >> 3) & 1) * 8;  // row in m16 tile
    int a_kb = (lane >> 4) * 16;                    // k-half byte offset
    int b_n  = (lane & 7) + (lane >> 4) * 8;        // row in n16 group
    int b_kb = ((lane >> 3) & 1) * 16;

    for (int it = 0; it < KITERS; ++it) {
        cp_wait<STAGES - 2>();
        __syncthreads();

        int s = it & (STAGES - 1);
        uint32_t sA = sb + s * STAGE_BYTES;
        uint32_t sB = sA + A_ST;

        if (it + STAGES - 1 < KITERS)
            load_stage((it + STAGES - 1) & (STAGES - 1), it + STAGES - 1);
        else
            cp_commit();   // uniform group accounting

        #pragma unroll
        for (int kc = 0; kc < 4; kc++) {
            uint32_t a[4][4];
            #pragma unroll
            for (int mt = 0; mt < 4; mt++) {
                int m_row = wm * 64 + mt * 16 + a_m;
                ldmatrix_x4(a[mt][0], a[mt][1], a[mt][2], a[mt][3],
                            sA + swz(m_row * 128 + kc * 32 + a_kb));
            }
            uint32_t b[8][2];
            #pragma unroll
            for (int ng = 0; ng < 4; ng++) {
                uint32_t r0, r1, r2, r3;
                int n_row = wn * 64 + ng * 16 + b_n;
                ldmatrix_x4(r0, r1, r2, r3,
                            sB + swz(n_row * 128 + kc * 32 + b_kb));
                b[ng * 2 + 0][0] = r0; b[ng * 2 + 0][1] = r1;
                b[ng * 2 + 1][0] = r2; b[ng * 2 + 1][1] = r3;
            }
            #pragma unroll
            for (int mt = 0; mt < 4; mt++)
                #pragma unroll
                for (int nt = 0; nt < 8; nt++)
                    mma16816(acc[mt][nt][0], acc[mt][nt][1],
                             acc[mt][nt][2], acc[mt][nt][3],
                             a[mt][0], a[mt][1], a[mt][2], a[mt][3],
                             b[nt][0], b[nt][1]);
        }
        __syncthreads();
    }

    // epilogue
    #pragma unroll
    for (int mt = 0; mt < 4; mt++) {
        int row0 = bm + wm * 64 + mt * 16 + (lane >> 2);
        #pragma unroll
        for (int nt = 0; nt < 8; nt++) {
            int col = bn + wn * 64 + nt * 8 + (lane & 3) * 2;
            float2 bv = *reinterpret_cast<const float2*>(bias + col);
            float2 v0 = {acc[mt][nt][0] + bv.x, acc[mt][nt][1] + bv.y};
            float2 v1 = {acc[mt][nt][2] + bv.x, acc[mt][nt][3] + bv.y};
            *reinterpret_cast<float2*>(out + (size_t)row0 * OUT_F + col) = v0;
            *reinterpret_cast<float2*>(out + (size_t)(row0 + 8) * OUT_F + col) = v1;
        }
    }
}

// ---------------------------------------------------------------------------
// Launch
// ---------------------------------------------------------------------------
extern "C" void kernel_launch(void* const* d_in, const int* in_sizes, int n_in,
                              void* d_out, int out_size) {
    const float* x    = (const float*)d_in[0];   // [8,2048,4096] f32
    const int*   q3   = (const int*)d_in[1];     // [524288,12] int32 bytes
    const float* norm = (const float*)d_in[2];   // [524288,1] f32
    const float* bias = (const float*)d_in[3];   // [4096] f32
    float* out = (float*)d_out;
    (void)in_sizes; (void)n_in; (void)out_size;

    convert_x_kernel<<<(M_TOT * (size_t)IN_F / 4) / 256, 256>>>(
        reinterpret_cast<const float4*>(x));
    dequant3_f16_kernel<<<(OUT_F * IN_F / 32) / 256, 256>>>(q3, norm);

    cudaFuncSetAttribute(gemm_hmma_kernel,
                         cudaFuncAttributeMaxDynamicSharedMemorySize, SMEM_TOTAL);
    dim3 grid(OUT_F / BN, M_TOT / BM);   // (16, 128)
    gemm_hmma_kernel<<<grid, THREADS, SMEM_TOTAL>>>(bias, out);
}

// round 11
// speedup vs baseline: 8.3808x; 1.0115x over previous
#include <cuda_runtime.h>
#include <cuda_fp16.h>
#include <cstdint>
#include <cstddef>

// ---------------------------------------------------------------------------
// Problem constants
// ---------------------------------------------------------------------------
#define IN_F   4096
#define OUT_F  4096
#define M_TOT  16384            // 8 * 2048

// GEMM tiling
#define BM 128
#define BN 256
#define BK 64
#define KITERS (IN_F / BK)      // 64
#define STAGES 4
#define THREADS 256
#define A_ST (BM * BK * 2)      // 16384 bytes
#define B_ST (BN * BK * 2)      // 32768 bytes
#define STAGE_BYTES (A_ST + B_ST)          // 49152
#define SMEM_TOTAL (STAGES * STAGE_BYTES)  // 196608

// fp16 staging buffers (static device globals: no allocation)
__device__ __half g_Xh[(size_t)M_TOT * IN_F];    // [m][k] k-contiguous
__device__ __half g_Wh[(size_t)OUT_F * IN_F];    // [o][k] k-contiguous

// ---------------------------------------------------------------------------
// helpers
// ---------------------------------------------------------------------------
__device__ __forceinline__ uint32_t smem_u32(const void* p) {
    uint32_t a;
    asm("{ .reg .u64 t; cvta.to.shared.u64 t, %1; cvt.u32.u64 %0, t; }"
        : "=r"(a) : "l"(p));
    return a;
}
// XOR swizzle for 128B rows: chunk(16B) index bits[6:4] ^= row bits[9:7]
__device__ __forceinline__ uint32_t swz(uint32_t byte_off) {
    return byte_off ^ ((byte_off >> 3) & 0x70);
}
__device__ __forceinline__ void cp_async16(uint32_t saddr, const void* gptr) {
    asm volatile("cp.async.cg.shared.global [%0], [%1], 16;"
                 :: "r"(saddr), "l"(gptr));
}
__device__ __forceinline__ void cp_commit() {
    asm volatile("cp.async.commit_group;");
}
template <int N>
__device__ __forceinline__ void cp_wait() {
    asm volatile("cp.async.wait_group %0;" :: "n"(N));
}
__device__ __forceinline__ void ldmatrix_x4(uint32_t& r0, uint32_t& r1,
                                            uint32_t& r2, uint32_t& r3,
                                            uint32_t addr) {
    asm volatile("ldmatrix.sync.aligned.m8n8.x4.shared.b16 {%0,%1,%2,%3}, [%4];"
                 : "=r"(r0), "=r"(r1), "=r"(r2), "=r"(r3) : "r"(addr));
}
__device__ __forceinline__ void mma16816(float& c0, float& c1, float& c2, float& c3,
                                         uint32_t a0, uint32_t a1, uint32_t a2, uint32_t a3,
                                         uint32_t b0, uint32_t b1) {
    asm volatile(
        "mma.sync.aligned.m16n8k16.row.col.f32.f16.f16.f32 "
        "{%0,%1,%2,%3}, {%4,%5,%6,%7}, {%8,%9}, {%0,%1,%2,%3};"
        : "+f"(c0), "+f"(c1), "+f"(c2), "+f"(c3)
        : "r"(a0), "r"(a1), "r"(a2), "r"(a3), "r"(b0), "r"(b1));
}

// ---------------------------------------------------------------------------
// Prekernel 1: x (fp32) -> g_Xh (fp16)
// ---------------------------------------------------------------------------
__global__ void convert_x_kernel(const float4* __restrict__ x4) {
    size_t i = (size_t)blockIdx.x * blockDim.x + threadIdx.x;
    float4 v = x4[i];
    __half2 h0 = __floats2half2_rn(v.x, v.y);
    __half2 h1 = __floats2half2_rn(v.z, v.w);
    __half2* dst = reinterpret_cast<__half2*>(g_Xh) + 2 * i;
    dst[0] = h0;
    dst[1] = h1;
}

// ---------------------------------------------------------------------------
// Prekernel 2: 3-bit dequant -> g_Wh fp16 [o][k]  (w = n*(2v-7)/7)
// ---------------------------------------------------------------------------
__global__ void dequant3_f16_kernel(const int* __restrict__ q3,
                                    const float* __restrict__ norm) {
    int g = blockIdx.x * blockDim.x + threadIdx.x;   // 524288 groups
    const uint4* q = reinterpret_cast<const uint4*>(q3 + (size_t)g * 12);
    uint4 qa = q[0], qb = q[1], qc = q[2];
    int by[12] = {(int)qa.x, (int)qa.y, (int)qa.z, (int)qa.w,
                  (int)qb.x, (int)qb.y, (int)qb.z, (int)qb.w,
                  (int)qc.x, (int)qc.y, (int)qc.z, (int)qc.w};
    float nm = norm[g];
    float s  = nm * (1.0f / 7.0f);

    __half hv[32];
    #pragma unroll
    for (int t = 0; t < 4; t++) {
        int b0 = by[3 * t + 0], b1 = by[3 * t + 1], b2 = by[3 * t + 2];
        int v[8];
        v[0] =  b0        & 7;
        v[1] = (b0 >> 3)  & 7;
        v[2] = ((b0 >> 6) & 3) | ((b1 & 1) << 2);
        v[3] = (b1 >> 1)  & 7;
        v[4] = (b1 >> 4)  & 7;
        v[5] = ((b1 >> 7) & 1) | ((b2 & 3) << 1);
        v[6] = (b2 >> 2)  & 7;
        v[7] = (b2 >> 5)  & 7;
        #pragma unroll
        for (int j = 0; j < 8; j++)
            hv[t * 8 + j] = __float2half_rn((float)(2 * v[j] - 7) * s);
    }
    uint4* dst = reinterpret_cast<uint4*>(g_Wh + (size_t)g * 32);
    const uint4* src = reinterpret_cast<const uint4*>(hv);
    dst[0] = src[0]; dst[1] = src[1]; dst[2] = src[2]; dst[3] = src[3];
}

// ---------------------------------------------------------------------------
// GEMM: out[m][n] = sum_k Xh[m][k]*Wh[n][k] + bias[n]
// mma.sync m16n8k16 + cp.async 4-stage pipeline.
// 8 warps, 2x4 layout: warp tile 64x64.
// One __syncthreads per K-iter; fragment double-buffering across k16 chunks.
// ---------------------------------------------------------------------------
__global__ __launch_bounds__(THREADS, 1)
void gemm_hmma_kernel(const float* __restrict__ bias,
                      float* __restrict__ out) {
    extern __shared__ char smem[];
    uint32_t sb = smem_u32(smem);

    int tid  = threadIdx.x;
    int wid  = tid >> 5;
    int lane = tid & 31;
    int wm = wid & 1;          // 0..1 -> 64-row slice
    int wn = wid >> 1;         // 0..3 -> 64-col slice

    int bm = blockIdx.y * BM;
    int bn = blockIdx.x * BN;

    const __half* gA = g_Xh + (size_t)bm * IN_F;
    const __half* gB = g_Wh + (size_t)bn * IN_F;

    auto load_stage = [&](int s, int it) {
        uint32_t sA = sb + s * STAGE_BYTES;
        uint32_t sB = sA + A_ST;
        int k0 = it * BK;
        #pragma unroll
        for (int i = 0; i < 4; i++) {
            int id  = tid + i * THREADS;
            int row = id >> 3;
            int c   = id & 7;
            cp_async16(sA + swz(row * 128 + c * 16),
                       gA + (size_t)row * IN_F + k0 + c * 8);
        }
        #pragma unroll
        for (int i = 0; i < 8; i++) {
            int id  = tid + i * THREADS;
            int row = id >> 3;
            int c   = id & 7;
            cp_async16(sB + swz(row * 128 + c * 16),
                       gB + (size_t)row * IN_F + k0 + c * 8);
        }
        cp_commit();
    };

    float acc[4][8][4];
    #pragma unroll
    for (int mt = 0; mt < 4; mt++)
        #pragma unroll
        for (int nt = 0; nt < 8; nt++)
            #pragma unroll
            for (int r = 0; r < 4; r++)
                acc[mt][nt][r] = 0.0f;

    // prologue
    #pragma unroll
    for (int s = 0; s < STAGES - 1; s++) load_stage(s, s);

    // ldmatrix lane addressing
    int a_m  = (lane & 7) + ((lane >> 3) & 1) * 8;
    int a_kb = (lane >> 4) * 16;
    int b_n  = (lane & 7) + (lane >> 4) * 8;
    int b_kb = ((lane >> 3) & 1) * 16;

    uint32_t a_frag[2][4][4];
    uint32_t b_frag[2][8][2];

    auto load_frags = [&](int buf, uint32_t sA, uint32_t sB, int kc) {
        #pragma unroll
        for (int mt = 0; mt < 4; mt++) {
            int m_row = wm * 64 + mt * 16 + a_m;
            ldmatrix_x4(a_frag[buf][mt][0], a_frag[buf][mt][1],
                        a_frag[buf][mt][2], a_frag[buf][mt][3],
                        sA + swz(m_row * 128 + kc * 32 + a_kb));
        }
        #pragma unroll
        for (int ng = 0; ng < 4; ng++) {
            uint32_t r0, r1, r2, r3;
            int n_row = wn * 64 + ng * 16 + b_n;
            ldmatrix_x4(r0, r1, r2, r3,
                        sB + swz(n_row * 128 + kc * 32 + b_kb));
            b_frag[buf][ng * 2 + 0][0] = r0; b_frag[buf][ng * 2 + 0][1] = r1;
            b_frag[buf][ng * 2 + 1][0] = r2; b_frag[buf][ng * 2 + 1][1] = r3;
        }
    };

    auto do_mmas = [&](int buf) {
        #pragma unroll
        for (int mt = 0; mt < 4; mt++)
            #pragma unroll
            for (int nt = 0; nt < 8; nt++)
                mma16816(acc[mt][nt][0], acc[mt][nt][1],
                         acc[mt][nt][2], acc[mt][nt][3],
                         a_frag[buf][mt][0], a_frag[buf][mt][1],
                         a_frag[buf][mt][2], a_frag[buf][mt][3],
                         b_frag[buf][nt][0], b_frag[buf][nt][1]);
    };

    for (int it = 0; it < KITERS; ++it) {
        cp_wait<STAGES - 2>();
        __syncthreads();
        // Single barrier per iter: loads below target the stage consumed in
        // it-1; the barrier guarantees every warp finished reading it.

        int s = it & (STAGES - 1);
        uint32_t sA = sb + s * STAGE_BYTES;
        uint32_t sB = sA + A_ST;

        if (it + STAGES - 1 < KITERS)
            load_stage((it + STAGES - 1) & (STAGES - 1), it + STAGES - 1);
        else
            cp_commit();   // uniform group accounting

        load_frags(0, sA, sB, 0);
        #pragma unroll
        for (int kc = 0; kc < 4; kc++) {
            if (kc < 3) load_frags((kc + 1) & 1, sA, sB, kc + 1);
            do_mmas(kc & 1);
        }
    }

    // epilogue
    #pragma unroll
    for (int mt = 0; mt < 4; mt++) {
        int row0 = bm + wm * 64 + mt * 16 + (lane >> 2);
        #pragma unroll
        for (int nt = 0; nt < 8; nt++) {
            int col = bn + wn * 64 + nt * 8 + (lane & 3) * 2;
            float2 bv = *reinterpret_cast<const float2*>(bias + col);
            float2 v0 = {acc[mt][nt][0] + bv.x, acc[mt][nt][1] + bv.y};
            float2 v1 = {acc[mt][nt][2] + bv.x, acc[mt][nt][3] + bv.y};
            *reinterpret_cast<float2*>(out + (size_t)row0 * OUT_F + col) = v0;
            *reinterpret_cast<float2*>(out + (size_t)(row0 + 8) * OUT_F + col) = v1;
        }
    }
}

// ---------------------------------------------------------------------------
// Launch
// ---------------------------------------------------------------------------
extern "C" void kernel_launch(void* const* d_in, const int* in_sizes, int n_in,
                              void* d_out, int out_size) {
    const float* x    = (const float*)d_in[0];   // [8,2048,4096] f32
    const int*   q3   = (const int*)d_in[1];     // [524288,12] int32 bytes
    const float* norm = (const float*)d_in[2];   // [524288,1] f32
    const float* bias = (const float*)d_in[3];   // [4096] f32
    float* out = (float*)d_out;
    (void)in_sizes; (void)n_in; (void)out_size;

    convert_x_kernel<<<(M_TOT * (size_t)IN_F / 4) / 256, 256>>>(
        reinterpret_cast<const float4*>(x));
    dequant3_f16_kernel<<<(OUT_F * IN_F / 32) / 256, 256>>>(q3, norm);

    cudaFuncSetAttribute(gemm_hmma_kernel,
                         cudaFuncAttributeMaxDynamicSharedMemorySize, SMEM_TOTAL);
    dim3 grid(OUT_F / BN, M_TOT / BM);   // (16, 128)
    gemm_hmma_kernel<<<grid, THREADS, SMEM_TOTAL>>>(bias, out);
}

// round 16
// speedup vs baseline: 8.8961x; 1.0615x over previous
#include <cuda_runtime.h>
#include <cuda_fp16.h>
#include <cstdint>
#include <cstddef>

// ---------------------------------------------------------------------------
// Problem constants
// ---------------------------------------------------------------------------
#define IN_F   4096
#define OUT_F  4096
#define M_TOT  16384            // 8 * 2048

// GEMM tiling
#define BM 128
#define BN 256
#define BK 64
#define KITERS (IN_F / BK)      // 64
#define STAGES 4
#define THREADS 256
#define A_ST (BM * BK * 2)      // 16384 bytes
#define B_ST (BN * BK * 2)      // 32768 bytes
#define STAGE_BYTES (A_ST + B_ST)          // 49152
#define SMEM_TOTAL (STAGES * STAGE_BYTES)  // 196608

// prep kernel split
#define X_BLOCKS (M_TOT * IN_F / 4 / 256)      // 65536 blocks convert x
#define G_BLOCKS (OUT_F * IN_F / 32 / 256)     // 2048 blocks dequant

// fp16 staging buffers (static device globals: no allocation)
__device__ __half g_Xh[(size_t)M_TOT * IN_F];    // [m][k] k-contiguous
__device__ __half g_Wh[(size_t)OUT_F * IN_F];    // [o][k] k-contiguous

// ---------------------------------------------------------------------------
// helpers
// ---------------------------------------------------------------------------
__device__ __forceinline__ uint32_t smem_u32(const void* p) {
    uint32_t a;
    asm("{ .reg .u64 t; cvta.to.shared.u64 t, %1; cvt.u32.u64 %0, t; }"
        : "=r"(a) : "l"(p));
    return a;
}
// XOR swizzle for 128B rows: chunk(16B) index bits[6:4] ^= row bits[9:7]
__device__ __forceinline__ uint32_t swz(uint32_t byte_off) {
    return byte_off ^ ((byte_off >> 3) & 0x70);
}
__device__ __forceinline__ void cp_async16(uint32_t saddr, const void* gptr) {
    asm volatile("cp.async.cg.shared.global [%0], [%1], 16;"
                 :: "r"(saddr), "l"(gptr));
}
__device__ __forceinline__ void cp_commit() {
    asm volatile("cp.async.commit_group;");
}
template <int N>
__device__ __forceinline__ void cp_wait() {
    asm volatile("cp.async.wait_group %0;" :: "n"(N));
}
__device__ __forceinline__ void ldmatrix_x4(uint32_t& r0, uint32_t& r1,
                                            uint32_t& r2, uint32_t& r3,
                                            uint32_t addr) {
    asm volatile("ldmatrix.sync.aligned.m8n8.x4.shared.b16 {%0,%1,%2,%3}, [%4];"
                 : "=r"(r0), "=r"(r1), "=r"(r2), "=r"(r3) : "r"(addr));
}
__device__ __forceinline__ void mma16816(float& c0, float& c1, float& c2, float& c3,
                                         uint32_t a0, uint32_t a1, uint32_t a2, uint32_t a3,
                                         uint32_t b0, uint32_t b1) {
    asm volatile(
        "mma.sync.aligned.m16n8k16.row.col.f32.f16.f16.f32 "
        "{%0,%1,%2,%3}, {%4,%5,%6,%7}, {%8,%9}, {%0,%1,%2,%3};"
        : "+f"(c0), "+f"(c1), "+f"(c2), "+f"(c3)
        : "r"(a0), "r"(a1), "r"(a2), "r"(a3), "r"(b0), "r"(b1));
}

// ---------------------------------------------------------------------------
// Merged prep kernel: blocks [0, X_BLOCKS) convert x fp32->fp16,
// blocks [X_BLOCKS, X_BLOCKS+G_BLOCKS) dequant 3-bit -> fp16.
// Both parts are DRAM-bound; merging lets them overlap instead of serialize.
// ---------------------------------------------------------------------------
__global__ void prep_kernel(const float4* __restrict__ x4,
                            const int* __restrict__ q3,
                            const float* __restrict__ norm) {
    int b = blockIdx.x;
    if (b < X_BLOCKS) {
        size_t i = (size_t)b * blockDim.x + threadIdx.x;
        float4 v = x4[i];
        __half2 h0 = __floats2half2_rn(v.x, v.y);
        __half2 h1 = __floats2half2_rn(v.z, v.w);
        __half2* dst = reinterpret_cast<__half2*>(g_Xh) + 2 * i;
        dst[0] = h0;
        dst[1] = h1;
    } else {
        int g = (b - X_BLOCKS) * blockDim.x + threadIdx.x;   // group index
        const uint4* q = reinterpret_cast<const uint4*>(q3 + (size_t)g * 12);
        uint4 qa = q[0], qb = q[1], qc = q[2];
        int by[12] = {(int)qa.x, (int)qa.y, (int)qa.z, (int)qa.w,
                      (int)qb.x, (int)qb.y, (int)qb.z, (int)qb.w,
                      (int)qc.x, (int)qc.y, (int)qc.z, (int)qc.w};
        float nm = norm[g];
        float s  = nm * (1.0f / 7.0f);

        __half hv[32];
        #pragma unroll
        for (int t = 0; t < 4; t++) {
            int b0 = by[3 * t + 0], b1 = by[3 * t + 1], b2 = by[3 * t + 2];
            int v[8];
            v[0] =  b0        & 7;
            v[1] = (b0 >> 3)  & 7;
            v[2] = ((b0 >> 6) & 3) | ((b1 & 1) << 2);
            v[3] = (b1 >> 1)  & 7;
            v[4] = (b1 >> 4)  & 7;
            v[5] = ((b1 >> 7) & 1) | ((b2 & 3) << 1);
            v[6] = (b2 >> 2)  & 7;
            v[7] = (b2 >> 5)  & 7;
            #pragma unroll
            for (int j = 0; j < 8; j++)
                hv[t * 8 + j] = __float2half_rn((float)(2 * v[j] - 7) * s);
        }
        uint4* dst = reinterpret_cast<uint4*>(g_Wh + (size_t)g * 32);
        const uint4* src = reinterpret_cast<const uint4*>(hv);
        dst[0] = src[0]; dst[1] = src[1]; dst[2] = src[2]; dst[3] = src[3];
    }
}

// ---------------------------------------------------------------------------
// GEMM: out[m][n] = sum_k Xh[m][k]*Wh[n][k] + bias[n]
// mma.sync m16n8k16 + cp.async 4-stage pipeline.
// 8 warps, 2x4 layout: warp tile 64x64.
// Cross-iteration fragment pipelining: the cp_wait + barrier + next-stage
// kc=0 fragment prefetch all happen under the kc==3 MMA burst of the
// previous iteration, so no iteration starts with a serial wait->ldsm chain.
// ---------------------------------------------------------------------------
__global__ __launch_bounds__(THREADS, 1)
void gemm_hmma_kernel(const float* __restrict__ bias,
                      float* __restrict__ out) {
    extern __shared__ char smem[];
    uint32_t sb = smem_u32(smem);

    int tid  = threadIdx.x;
    int wid  = tid >> 5;
    int lane = tid & 31;
    int wm = wid & 1;          // 0..1 -> 64-row slice
    int wn = wid >> 1;         // 0..3 -> 64-col slice

    int bm = blockIdx.y * BM;
    int bn = blockIdx.x * BN;

    const __half* gA = g_Xh + (size_t)bm * IN_F;
    const __half* gB = g_Wh + (size_t)bn * IN_F;

    auto load_stage = [&](int s, int it) {
        uint32_t sA = sb + s * STAGE_BYTES;
        uint32_t sB = sA + A_ST;
        int k0 = it * BK;
        #pragma unroll
        for (int i = 0; i < 4; i++) {
            int id  = tid + i * THREADS;
            int row = id >> 3;
            int c   = id & 7;
            cp_async16(sA + swz(row * 128 + c * 16),
                       gA + (size_t)row * IN_F + k0 + c * 8);
        }
        #pragma unroll
        for (int i = 0; i < 8; i++) {
            int id  = tid + i * THREADS;
            int row = id >> 3;
            int c   = id & 7;
            cp_async16(sB + swz(row * 128 + c * 16),
                       gB + (size_t)row * IN_F + k0 + c * 8);
        }
        cp_commit();
    };

    float acc[4][8][4];
    #pragma unroll
    for (int mt = 0; mt < 4; mt++)
        #pragma unroll
        for (int nt = 0; nt < 8; nt++)
            #pragma unroll
            for (int r = 0; r < 4; r++)
                acc[mt][nt][r] = 0.0f;

    // prologue: fill stages 0..2
    #pragma unroll
    for (int s = 0; s < STAGES - 1; s++) load_stage(s, s);

    // ldmatrix lane addressing
    int a_m  = (lane & 7) + ((lane >> 3) & 1) * 8;
    int a_kb = (lane >> 4) * 16;
    int b_n  = (lane & 7) + (lane >> 4) * 8;
    int b_kb = ((lane >> 3) & 1) * 16;

    uint32_t a_frag[2][4][4];
    uint32_t b_frag[2][8][2];

    auto load_frags = [&](int buf, uint32_t sA, uint32_t sB, int kc) {
        #pragma unroll
        for (int mt = 0; mt < 4; mt++) {
            int m_row = wm * 64 + mt * 16 + a_m;
            ldmatrix_x4(a_frag[buf][mt][0], a_frag[buf][mt][1],
                        a_frag[buf][mt][2], a_frag[buf][mt][3],
                        sA + swz(m_row * 128 + kc * 32 + a_kb));
        }
        #pragma unroll
        for (int ng = 0; ng < 4; ng++) {
            uint32_t r0, r1, r2, r3;
            int n_row = wn * 64 + ng * 16 + b_n;
            ldmatrix_x4(r0, r1, r2, r3,
                        sB + swz(n_row * 128 + kc * 32 + b_kb));
            b_frag[buf][ng * 2 + 0][0] = r0; b_frag[buf][ng * 2 + 0][1] = r1;
            b_frag[buf][ng * 2 + 1][0] = r2; b_frag[buf][ng * 2 + 1][1] = r3;
        }
    };

    auto do_mmas = [&](int buf) {
        #pragma unroll
        for (int mt = 0; mt < 4; mt++)
            #pragma unroll
            for (int nt = 0; nt < 8; nt++)
                mma16816(acc[mt][nt][0], acc[mt][nt][1],
                         acc[mt][nt][2], acc[mt][nt][3],
                         a_frag[buf][mt][0], a_frag[buf][mt][1],
                         a_frag[buf][mt][2], a_frag[buf][mt][3],
                         b_frag[buf][nt][0], b_frag[buf][nt][1]);
    };

    // prologue handoff: stage 0 ready -> prefetch its kc=0 fragments
    cp_wait<STAGES - 2>();
    __syncthreads();
    load_frags(0, sb, sb + A_ST, 0);

    for (int it = 0; it < KITERS; ++it) {
        int s = it & (STAGES - 1);
        uint32_t sA = sb + s * STAGE_BYTES;
        uint32_t sB = sA + A_ST;

        // overwrite stage (it+3)%4 == (it-1)%4: all reads of it-1 completed
        // before the barrier inside iter it-1's kc==3 slot.
        if (it + STAGES - 1 < KITERS)
            load_stage((it + STAGES - 1) & (STAGES - 1), it + STAGES - 1);
        else
            cp_commit();   // uniform group accounting

        #pragma unroll
        for (int kc = 0; kc < 4; kc++) {
            if (kc < 3) {
                load_frags((kc + 1) & 1, sA, sB, kc + 1);
            } else if (it + 1 < KITERS) {
                // next stage (group it+1) is complete after wait<2>;
                // barrier gives cross-thread visibility AND separates the
                // reads of stage `it` from next iteration's overwrite.
                cp_wait<STAGES - 2>();
                __syncthreads();
                uint32_t nA = sb + ((it + 1) & (STAGES - 1)) * STAGE_BYTES;
                load_frags(0, nA, nA + A_ST, 0);
            }
            do_mmas(kc & 1);
        }
    }

    // epilogue
    #pragma unroll
    for (int mt = 0; mt < 4; mt++) {
        int row0 = bm + wm * 64 + mt * 16 + (lane >> 2);
        #pragma unroll
        for (int nt = 0; nt < 8; nt++) {
            int col = bn + wn * 64 + nt * 8 + (lane & 3) * 2;
            float2 bv = *reinterpret_cast<const float2*>(bias + col);
            float2 v0 = {acc[mt][nt][0] + bv.x, acc[mt][nt][1] + bv.y};
            float2 v1 = {acc[mt][nt][2] + bv.x, acc[mt][nt][3] + bv.y};
            *reinterpret_cast<float2*>(out + (size_t)row0 * OUT_F + col) = v0;
            *reinterpret_cast<float2*>(out + (size_t)(row0 + 8) * OUT_F + col) = v1;
        }
    }
}

// ---------------------------------------------------------------------------
// Launch
// ---------------------------------------------------------------------------
extern "C" void kernel_launch(void* const* d_in, const int* in_sizes, int n_in,
                              void* d_out, int out_size) {
    const float* x    = (const float*)d_in[0];   // [8,2048,4096] f32
    const int*   q3   = (const int*)d_in[1];     // [524288,12] int32 bytes
    const float* norm = (const float*)d_in[2];   // [524288,1] f32
    const float* bias = (const float*)d_in[3];   // [4096] f32
    float* out = (float*)d_out;
    (void)in_sizes; (void)n_in; (void)out_size;

    prep_kernel<<<X_BLOCKS + G_BLOCKS, 256>>>(
        reinterpret_cast<const float4*>(x), q3, norm);

    cudaFuncSetAttribute(gemm_hmma_kernel,
                         cudaFuncAttributeMaxDynamicSharedMemorySize, SMEM_TOTAL);
    dim3 grid(OUT_F / BN, M_TOT / BM);   // (16, 128)
    gemm_hmma_kernel<<<grid, THREADS, SMEM_TOTAL>>>(bias, out);
}